// round 9
// baseline (speedup 1.0000x reference)
#include <cuda_runtime.h>
#include <cuda_bf16.h>

// Problem constants (fixed by the reference: B=512, V=32768, C=16)
#define BB   512
#define VV   32768
#define CC   16
#define TPB  256
#define SPLIT 8
#define BPS  (BB / SPLIT)      // 64 samples per split
#define VBLOCKS (VV / TPB)     // 128 v-tiles

// Deterministic scratch: per-split partial sums [SPLIT][C][V] (16 MB).
__device__ float g_partial[(size_t)SPLIT * CC * VV];

// ---------------------------------------------------------------------------
// Kernel 1: gather + |sv*w| + segment-sum into per-split partials.
// Grid (VBLOCKS, SPLIT); each thread owns one v column for 64 b's,
// accumulating in smem[class][tid]. Measured DRAM-bound at ~87% of peak
// against a ~1.15 GB mandatory-traffic floor (W_eff gather = 1 float per
// 64B burst). FROZEN — do not perturb without re-deriving the traffic model.
// ---------------------------------------------------------------------------
__global__ __launch_bounds__(TPB) void accum_kernel(
    const float* __restrict__ sv,
    const float* __restrict__ W,
    const int*   __restrict__ labels)
{
    __shared__ float acc[CC][TPB];
    __shared__ int   slab[BPS];

    const int tid   = threadIdx.x;
    const int v     = blockIdx.x * TPB + tid;
    const int split = blockIdx.y;
    const int b0    = split * BPS;

    if (tid < BPS) slab[tid] = labels[b0 + tid];
#pragma unroll
    for (int c = 0; c < CC; ++c) acc[c][tid] = 0.0f;
    __syncthreads();

    const float* svp = sv + (size_t)b0 * VV + v;
    const float* Wp  = W  + ((size_t)b0 * VV + v) * CC;

    // 8 b's per batch: 16 independent global loads in flight per thread.
#pragma unroll 1
    for (int bb = 0; bb < BPS; bb += 8) {
        int   l[8];
        float s[8];
        float w[8];
#pragma unroll
        for (int k = 0; k < 8; ++k) l[k] = slab[bb + k];
#pragma unroll
        for (int k = 0; k < 8; ++k)
            s[k] = __ldcs(svp + (size_t)(bb + k) * VV);
#pragma unroll
        for (int k = 0; k < 8; ++k)
            w[k] = __ldcs(Wp + (size_t)(bb + k) * VV * CC + l[k]);
#pragma unroll
        for (int k = 0; k < 8; ++k)
            acc[l[k]][tid] += fabsf(s[k] * w[k]);
    }

    // Coalesced partial write (fully written -> no zeroing needed).
    float* outp = g_partial + ((size_t)split * CC) * VV + v;
#pragma unroll
    for (int c = 0; c < CC; ++c)
        outp[(size_t)c * VV] = acc[c][tid];
}

// ---------------------------------------------------------------------------
// Kernel 2: fused count + init-decode + split-reduce + mean + EMA.
// Software-pipelined: the 8 independent partial float2 loads + centroid load
// issue FIRST; the label-count / init-sniff / __syncthreads serialization
// (R8's binder: block critical path = sync chain THEN loads) overlaps with
// those loads in flight. One barrier instead of two.
// Each block's 512 contiguous outputs lie in exactly one class c.
// ---------------------------------------------------------------------------
__global__ __launch_bounds__(256) void finalize_kernel(
    const float*         __restrict__ centroids,
    const int*           __restrict__ labels,
    const unsigned char* __restrict__ initp,
    float*               __restrict__ out)
{
    const int idx2 = blockIdx.x * blockDim.x + threadIdx.x;   // over C*V/2
    const int idx  = idx2 * 2;
    const int c    = idx >> 15;          // /V  (constant within a block)
    const int v    = idx & (VV - 1);

    __shared__ int s_cnt;
    __shared__ int s_ini;

    // ---- Phase A: fire all global loads (no block-shared dependencies) ----
    float2 t[SPLIT];
#pragma unroll
    for (int p = 0; p < SPLIT; ++p)
        t[p] = *(const float2*)&g_partial[((size_t)p * CC + c) * VV + v];
    const float2 ct = *(const float2*)&centroids[idx];

    // ---- Phase B: count + sniff while loads are in flight ----
    if (threadIdx.x == 0) s_cnt = 0;
    __syncthreads();                      // orders the s_cnt=0 init

    int my = 0;
#pragma unroll
    for (int b = threadIdx.x; b < BB; b += 256)
        my += (labels[b] == c);
    if (my) atomicAdd(&s_cnt, my);

    if (threadIdx.x == 0) {
        const int4  i4 = *(const int4*)initp;          // first 16 bytes
        const unsigned char* bp = (const unsigned char*)&i4;
        bool i32like = true, f32like = true, anyNZ = false;
        for (int i = 0; i < 16; ++i) {
            if ((i & 3) != 0 && bp[i] != 0) i32like = false;
            if (bp[i] != 0) anyNZ = true;
        }
        const float* fp = (const float*)&i4;
        for (int k = 0; k < 4; ++k)
            if (!(fp[k] == 0.0f || fp[k] == 1.0f)) f32like = false;

        int ini;
        if (!anyNZ)       ini = 0;                     // all-zero: representations agree
        else if (f32like) ini = (((const float*)initp)[c] != 0.0f);
        else if (i32like) ini = (((const int*)initp)[c] != 0);
        else              ini = (initp[c] != 0);
        s_ini = ini;
    }
    __syncthreads();

    const int cnt = s_cnt;
    const int ini = s_ini;

    // ---- Phase C: combine (loads long since landed) ----
    float2 s = make_float2(0.f, 0.f);
#pragma unroll
    for (int p = 0; p < SPLIT; ++p) { s.x += t[p].x; s.y += t[p].y; }

    const float inv   = 1.0f / fmaxf((float)cnt, 1.0f);
    const float ALPHA = (float)(2.0 / 1001.0);  // 1 - MOMENTUM

    float2 r;
    {
        float m, u;
        m = s.x * inv; u = ini ? (ct.x + ALPHA * (m - ct.x)) : m; r.x = cnt > 0 ? u : ct.x;
        m = s.y * inv; u = ini ? (ct.y + ALPHA * (m - ct.y)) : m; r.y = cnt > 0 ? u : ct.y;
    }
    *(float2*)&out[idx] = r;
}

// ---------------------------------------------------------------------------
// Launch. Inputs bound by UNIQUE element count (robust to metadata order):
//   sparse_vector f32 [B,V]     -> 16,777,216
//   W_eff         f32 [B,V,C]   -> 268,435,456
//   labels        i32 [B]       -> 512
//   centroids     f32 [C,V]     -> 524,288
//   initialized   bool[C]       -> 16
// ---------------------------------------------------------------------------
extern "C" void kernel_launch(void* const* d_in, const int* in_sizes, int n_in,
                              void* d_out, int out_size)
{
    const float*         sv   = nullptr;
    const float*         W    = nullptr;
    const int*           lab  = nullptr;
    const float*         cent = nullptr;
    const unsigned char* init = nullptr;

    for (int i = 0; i < n_in; ++i) {
        long n = (long)in_sizes[i];
        if      (n == (long)BB * VV)       sv   = (const float*)d_in[i];
        else if (n == (long)BB * VV * CC)  W    = (const float*)d_in[i];
        else if (n == (long)BB)            lab  = (const int*)d_in[i];
        else if (n == (long)CC * VV)       cent = (const float*)d_in[i];
        else if (n == (long)CC)            init = (const unsigned char*)d_in[i];
    }
    if (!sv)   sv   = (const float*)d_in[0];
    if (!W)    W    = (const float*)d_in[1];
    if (!lab)  lab  = (const int*)d_in[2];
    if (!cent) cent = (const float*)d_in[3];
    if (!init) init = (const unsigned char*)d_in[4];

    float* out = (float*)d_out;

    accum_kernel<<<dim3(VBLOCKS, SPLIT), TPB>>>(sv, W, lab);
    finalize_kernel<<<(CC * VV / 2) / 256, 256>>>(cent, lab, init, out);
}

// round 10
// speedup vs baseline: 1.0034x; 1.0034x over previous
#include <cuda_runtime.h>
#include <cuda_bf16.h>

// Problem constants (fixed by the reference: B=512, V=32768, C=16)
#define BB   512
#define VV   32768
#define CC   16
#define TPB  128               // 128 threads/block (v-tile width)
#define SPLIT 4                // 4 b-splits -> halves partial traffic vs 8
#define BPS  (BB / SPLIT)      // 128 samples per split
#define VBLOCKS (VV / TPB)     // 256 v-tiles -> grid (256,4) = 1024 blocks
                               // (keeps the validated 7-blocks/worst-SM balance)

// Deterministic scratch: per-split partial sums [SPLIT][C][V] (8 MB).
__device__ float g_partial[(size_t)SPLIT * CC * VV];

// ---------------------------------------------------------------------------
// Kernel 1: gather + |sv*w| + segment-sum into per-split partials.
// Grid (VBLOCKS, SPLIT); each thread owns one v column for 128 b's,
// accumulating in smem[class][tid] (same class across warp -> broadcast LDS
// + conflict-free STS). The gather core is byte-identical in access pattern
// to the version measured DRAM-bound at 87% of peak (~1.15 GB floor,
// W_eff = 1 float per 64B burst); this round only halves the partial-write
// term (16 MB -> 8 MB) while preserving grid balance (1024 blocks).
// ---------------------------------------------------------------------------
__global__ __launch_bounds__(TPB) void accum_kernel(
    const float* __restrict__ sv,
    const float* __restrict__ W,
    const int*   __restrict__ labels)
{
    __shared__ float acc[CC][TPB];
    __shared__ int   slab[BPS];

    const int tid   = threadIdx.x;
    const int v     = blockIdx.x * TPB + tid;
    const int split = blockIdx.y;
    const int b0    = split * BPS;

    slab[tid] = labels[b0 + tid];          // BPS == TPB == 128
#pragma unroll
    for (int c = 0; c < CC; ++c) acc[c][tid] = 0.0f;
    __syncthreads();

    const float* svp = sv + (size_t)b0 * VV + v;
    const float* Wp  = W  + ((size_t)b0 * VV + v) * CC;

    // 8 b's per batch: 16 independent global loads in flight per thread.
#pragma unroll 1
    for (int bb = 0; bb < BPS; bb += 8) {
        int   l[8];
        float s[8];
        float w[8];
#pragma unroll
        for (int k = 0; k < 8; ++k) l[k] = slab[bb + k];
#pragma unroll
        for (int k = 0; k < 8; ++k)
            s[k] = __ldcs(svp + (size_t)(bb + k) * VV);
#pragma unroll
        for (int k = 0; k < 8; ++k)
            w[k] = __ldcs(Wp + (size_t)(bb + k) * VV * CC + l[k]);
#pragma unroll
        for (int k = 0; k < 8; ++k)
            acc[l[k]][tid] += fabsf(s[k] * w[k]);
    }

    // Coalesced partial write (fully written -> no zeroing needed).
    float* outp = g_partial + ((size_t)split * CC) * VV + v;
#pragma unroll
    for (int c = 0; c < CC; ++c)
        outp[(size_t)c * VV] = acc[c][tid];
}

// ---------------------------------------------------------------------------
// Kernel 2: fused count + init-decode + split-reduce + mean + EMA.
// float2 granularity, 1024 blocks of 256. Loads fired first (independent),
// count/sniff overlap them. Now only 4 partial streams (8 MB total read).
// Each block's 512 contiguous outputs lie in exactly one class c.
// ---------------------------------------------------------------------------
__global__ __launch_bounds__(256) void finalize_kernel(
    const float*         __restrict__ centroids,
    const int*           __restrict__ labels,
    const unsigned char* __restrict__ initp,
    float*               __restrict__ out)
{
    const int idx2 = blockIdx.x * blockDim.x + threadIdx.x;   // over C*V/2
    const int idx  = idx2 * 2;
    const int c    = idx >> 15;          // /V  (constant within a block)
    const int v    = idx & (VV - 1);

    __shared__ int s_cnt;
    __shared__ int s_ini;

    // ---- Phase A: fire all global loads (no block-shared dependencies) ----
    float2 t[SPLIT];
#pragma unroll
    for (int p = 0; p < SPLIT; ++p)
        t[p] = *(const float2*)&g_partial[((size_t)p * CC + c) * VV + v];
    const float2 ct = *(const float2*)&centroids[idx];

    // ---- Phase B: count + sniff while loads are in flight ----
    if (threadIdx.x == 0) s_cnt = 0;
    __syncthreads();                      // orders the s_cnt=0 init

    int my = 0;
#pragma unroll
    for (int b = threadIdx.x; b < BB; b += 256)
        my += (labels[b] == c);
    if (my) atomicAdd(&s_cnt, my);

    if (threadIdx.x == 0) {
        const int4  i4 = *(const int4*)initp;          // first 16 bytes
        const unsigned char* bp = (const unsigned char*)&i4;
        bool i32like = true, f32like = true, anyNZ = false;
        for (int i = 0; i < 16; ++i) {
            if ((i & 3) != 0 && bp[i] != 0) i32like = false;
            if (bp[i] != 0) anyNZ = true;
        }
        const float* fp = (const float*)&i4;
        for (int k = 0; k < 4; ++k)
            if (!(fp[k] == 0.0f || fp[k] == 1.0f)) f32like = false;

        int ini;
        if (!anyNZ)       ini = 0;                     // all-zero: representations agree
        else if (f32like) ini = (((const float*)initp)[c] != 0.0f);
        else if (i32like) ini = (((const int*)initp)[c] != 0);
        else              ini = (initp[c] != 0);
        s_ini = ini;
    }
    __syncthreads();

    const int cnt = s_cnt;
    const int ini = s_ini;

    // ---- Phase C: combine ----
    float2 s = make_float2(0.f, 0.f);
#pragma unroll
    for (int p = 0; p < SPLIT; ++p) { s.x += t[p].x; s.y += t[p].y; }

    const float inv   = 1.0f / fmaxf((float)cnt, 1.0f);
    const float ALPHA = (float)(2.0 / 1001.0);  // 1 - MOMENTUM

    float2 r;
    {
        float m, u;
        m = s.x * inv; u = ini ? (ct.x + ALPHA * (m - ct.x)) : m; r.x = cnt > 0 ? u : ct.x;
        m = s.y * inv; u = ini ? (ct.y + ALPHA * (m - ct.y)) : m; r.y = cnt > 0 ? u : ct.y;
    }
    *(float2*)&out[idx] = r;
}

// ---------------------------------------------------------------------------
// Launch. Inputs bound by UNIQUE element count (robust to metadata order):
//   sparse_vector f32 [B,V]     -> 16,777,216
//   W_eff         f32 [B,V,C]   -> 268,435,456
//   labels        i32 [B]       -> 512
//   centroids     f32 [C,V]     -> 524,288
//   initialized   bool[C]       -> 16
// ---------------------------------------------------------------------------
extern "C" void kernel_launch(void* const* d_in, const int* in_sizes, int n_in,
                              void* d_out, int out_size)
{
    const float*         sv   = nullptr;
    const float*         W    = nullptr;
    const int*           lab  = nullptr;
    const float*         cent = nullptr;
    const unsigned char* init = nullptr;

    for (int i = 0; i < n_in; ++i) {
        long n = (long)in_sizes[i];
        if      (n == (long)BB * VV)       sv   = (const float*)d_in[i];
        else if (n == (long)BB * VV * CC)  W    = (const float*)d_in[i];
        else if (n == (long)BB)            lab  = (const int*)d_in[i];
        else if (n == (long)CC * VV)       cent = (const float*)d_in[i];
        else if (n == (long)CC)            init = (const unsigned char*)d_in[i];
    }
    if (!sv)   sv   = (const float*)d_in[0];
    if (!W)    W    = (const float*)d_in[1];
    if (!lab)  lab  = (const int*)d_in[2];
    if (!cent) cent = (const float*)d_in[3];
    if (!init) init = (const unsigned char*)d_in[4];

    float* out = (float*)d_out;

    accum_kernel<<<dim3(VBLOCKS, SPLIT), TPB>>>(sv, W, lab);
    finalize_kernel<<<(CC * VV / 2) / 256, 256>>>(cent, lab, init, out);
}